// round 15
// baseline (speedup 1.0000x reference)
#include <cuda_runtime.h>
#include <cuda_bf16.h>
#include <stdint.h>

// Dataset-fixed: N=100000, T=25, DEGS=4, G=512, E=8000000, indices int32
#define TPB    256
#define VEC    4                     // edges per thread per inner iteration
#define ITERS  2                     // inner iterations per tile
#define TILE   (TPB * VEC * ITERS)   // 2048 edges per block -> 3907 blocks
#define NMAX   100000
#define TT     625                   // 25*25

__device__ float4 g_nodes[NMAX];    // {pos.x, pos.y, pos.z, bitcast(atom_type)}

// ---------------------------------------------------------------------------
// Prep: zero output, pack node table.
// ---------------------------------------------------------------------------
__global__ void prep_kernel(const float* __restrict__ pos,
                            const int* __restrict__ atom_types,
                            float* __restrict__ out,
                            int N, int G)
{
    int i = blockIdx.x * blockDim.x + threadIdx.x;
    if (i < N) {
        float4 v;
        v.x = pos[3 * i + 0];
        v.y = pos[3 * i + 1];
        v.z = pos[3 * i + 2];
        v.w = __int_as_float(atom_types[i]);
        g_nodes[i] = v;
    }
    if (i < G) out[i] = 0.0f;
}

// ---------------------------------------------------------------------------
// Shared fragments
// ---------------------------------------------------------------------------
#define EDGE_V(II, JJ, VOUT)                                               \
    do {                                                                   \
        float4 p = __ldg(nodes + (II));                                    \
        float4 q = __ldg(nodes + (JJ));                                    \
        float dx = p.x - q.x, dy = p.y - q.y, dz = p.z - q.z;              \
        float r2 = fmaf(dx, dx, fmaf(dy, dy, dz * dz));                    \
        float x  = sqrtf(r2);                                              \
        int idx  = __float_as_int(p.w) * 25 + __float_as_int(q.w);         \
        float4 k = sk[idx];                                                \
        float  c = sv[idx];                                                \
        (VOUT) = fmaf(x, fmaf(x, fmaf(x, fmaf(x, k.w, k.z), k.y), k.x), c);\
    } while (0)

// Segment handling via direct batch value: flush accumulator on change.
// batch is sorted, so per-thread seg is non-decreasing.
#define HANDLE1(BI, VVAL)                                                  \
    do {                                                                   \
        if ((BI) != seg) {                                                 \
            if (acc != 0.0f) atomicAdd(&out[seg], acc);                    \
            acc = 0.0f;                                                    \
            seg = (BI);                                                    \
        }                                                                  \
        acc += (VVAL);                                                     \
    } while (0)

// Warp-aggregated final flush: one atomic per warp when segment is uniform.
__device__ __forceinline__ void flush_acc(float* __restrict__ out, int seg, float acc)
{
    const unsigned full = 0xFFFFFFFFu;
    int seg0 = __shfl_sync(full, seg, 0);
    bool uniform = __all_sync(full, seg == seg0);
    if (uniform) {
        #pragma unroll
        for (int o = 16; o > 0; o >>= 1)
            acc += __shfl_xor_sync(full, acc, o);
        if ((threadIdx.x & 31) == 0 && acc != 0.0f && seg0 >= 0)
            atomicAdd(&out[seg0], acc);
    } else {
        if (acc != 0.0f && seg >= 0) atomicAdd(&out[seg], acc);
    }
}

// ---------------------------------------------------------------------------
// Edge kernel (int32)
// ---------------------------------------------------------------------------
__global__ void __launch_bounds__(TPB, 8)
edge_kernel(const int* __restrict__ map0,
            const int* __restrict__ map1,
            const int* __restrict__ batch,
            const float* __restrict__ ks,     // [4,25,25]
            const float* __restrict__ v0t,    // [25,25]
            float* __restrict__ out,
            int E)
{
    __shared__ float4 sk[TT];
    __shared__ float  sv[TT];

    const int tid = threadIdx.x;
    for (int i = tid; i < TT; i += TPB) {
        sk[i] = make_float4(ks[i], ks[TT + i], ks[2 * TT + i], ks[3 * TT + i]);
        sv[i] = v0t[i];
    }
    __syncthreads();

    const int tile = blockIdx.x * TILE;
    if (tile >= E) return;

    int   seg = -1;      // sentinel: first HANDLE always sets it
    float acc = 0.0f;

    const float4* __restrict__ nodes = g_nodes;

    if (tile + TILE <= E) {
        #pragma unroll
        for (int it = 0; it < ITERS; ++it) {
            const int e = tile + it * (TPB * VEC) + tid * VEC;
            int4 ia = __ldcs((const int4*)(map0 + e));
            int4 ja = __ldcs((const int4*)(map1 + e));
            int4 bt = __ldcs((const int4*)(batch + e));

            float V0, V1, V2, V3;
            EDGE_V(ia.x, ja.x, V0);
            EDGE_V(ia.y, ja.y, V1);
            EDGE_V(ia.z, ja.z, V2);
            EDGE_V(ia.w, ja.w, V3);

            if (bt.w == seg) {                 // sorted => whole group == seg
                acc += (V0 + V1) + (V2 + V3);
            } else {
                HANDLE1(bt.x, V0);
                HANDLE1(bt.y, V1);
                HANDLE1(bt.z, V2);
                HANDLE1(bt.w, V3);
            }
        }
    } else {
        for (int it = 0; it < ITERS; ++it) {
            int e = tile + it * (TPB * VEC) + tid * VEC;
            for (int kk = 0; kk < VEC; ++kk) {
                int ee = e + kk;
                if (ee >= E) break;
                int ii = __ldcs(map0 + ee);
                int jj = __ldcs(map1 + ee);
                int bi = __ldcs(batch + ee);
                float V;
                EDGE_V(ii, jj, V);
                HANDLE1(bi, V);
            }
        }
    }

    flush_acc(out, seg, acc);
}

// ---------------------------------------------------------------------------
// Launch
// ---------------------------------------------------------------------------
extern "C" void kernel_launch(void* const* d_in, const int* in_sizes, int n_in,
                              void* d_out, int out_size)
{
    const float* pos        = (const float*)d_in[0];
    const float* ks         = (const float*)d_in[1];
    const float* v0t        = (const float*)d_in[2];
    const int*   mapping    = (const int*)d_in[3];
    const int*   atom_types = (const int*)d_in[4];
    const int*   batch      = (const int*)d_in[5];

    const int N = in_sizes[0] / 3;
    const int E = in_sizes[3] / 2;
    const int G = out_size;

    float* out = (float*)d_out;

    int prepThreads = (N > G) ? N : G;
    int prepBlocks  = (prepThreads + TPB - 1) / TPB;
    prep_kernel<<<prepBlocks, TPB>>>(pos, atom_types, out, N, G);

    int blocks = (E + TILE - 1) / TILE;
    edge_kernel<<<blocks, TPB>>>(mapping, mapping + E, batch, ks, v0t, out, E);
}

// round 16
// speedup vs baseline: 1.0247x; 1.0247x over previous
#include <cuda_runtime.h>
#include <cuda_bf16.h>
#include <stdint.h>

// Dataset-fixed: N=100000, T=25, DEGS=4, G=512, E=8000000, indices int32
#define TPB    256
#define VEC    4                     // edges per thread per inner iteration
#define ITERS  4                     // inner iterations per tile
#define TILE   (TPB * VEC * ITERS)   // 4096 edges per block -> 1954 blocks
#define NMAX   100000
#define TT     625                   // 25*25

__device__ float4 g_nodes[NMAX];    // {pos.x, pos.y, pos.z, bitcast(atom_type)}

// ---------------------------------------------------------------------------
// Prep: zero output, pack node table.
// ---------------------------------------------------------------------------
__global__ void prep_kernel(const float* __restrict__ pos,
                            const int* __restrict__ atom_types,
                            float* __restrict__ out,
                            int N, int G)
{
    int i = blockIdx.x * blockDim.x + threadIdx.x;
    if (i < N) {
        float4 v;
        v.x = pos[3 * i + 0];
        v.y = pos[3 * i + 1];
        v.z = pos[3 * i + 2];
        v.w = __int_as_float(atom_types[i]);
        g_nodes[i] = v;
    }
    if (i < G) out[i] = 0.0f;
}

// ---------------------------------------------------------------------------
// Shared fragments
// ---------------------------------------------------------------------------
#define EDGE_V(II, JJ, VOUT)                                               \
    do {                                                                   \
        float4 p = __ldg(nodes + (II));                                    \
        float4 q = __ldg(nodes + (JJ));                                    \
        float dx = p.x - q.x, dy = p.y - q.y, dz = p.z - q.z;              \
        float r2 = fmaf(dx, dx, fmaf(dy, dy, dz * dz));                    \
        float x  = sqrtf(r2);                                              \
        int idx  = __float_as_int(p.w) * 25 + __float_as_int(q.w);         \
        float4 k = sk[idx];                                                \
        float  c = sv[idx];                                                \
        (VOUT) = fmaf(x, fmaf(x, fmaf(x, fmaf(x, k.w, k.z), k.y), k.x), c);\
    } while (0)

// Segment handling via direct batch value: flush accumulator on change.
// batch is sorted, so per-thread seg is non-decreasing.
#define HANDLE1(BI, VVAL)                                                  \
    do {                                                                   \
        if ((BI) != seg) {                                                 \
            if (acc != 0.0f) atomicAdd(&out[seg], acc);                    \
            acc = 0.0f;                                                    \
            seg = (BI);                                                    \
        }                                                                  \
        acc += (VVAL);                                                     \
    } while (0)

// Warp-aggregated final flush: one atomic per warp when segment is uniform.
__device__ __forceinline__ void flush_acc(float* __restrict__ out, int seg, float acc)
{
    const unsigned full = 0xFFFFFFFFu;
    int seg0 = __shfl_sync(full, seg, 0);
    bool uniform = __all_sync(full, seg == seg0);
    if (uniform) {
        #pragma unroll
        for (int o = 16; o > 0; o >>= 1)
            acc += __shfl_xor_sync(full, acc, o);
        if ((threadIdx.x & 31) == 0 && acc != 0.0f && seg0 >= 0)
            atomicAdd(&out[seg0], acc);
    } else {
        if (acc != 0.0f && seg >= 0) atomicAdd(&out[seg], acc);
    }
}

// ---------------------------------------------------------------------------
// Edge kernel (int32)
// ---------------------------------------------------------------------------
__global__ void __launch_bounds__(TPB, 8)
edge_kernel(const int* __restrict__ map0,
            const int* __restrict__ map1,
            const int* __restrict__ batch,
            const float* __restrict__ ks,     // [4,25,25]
            const float* __restrict__ v0t,    // [25,25]
            float* __restrict__ out,
            int E)
{
    __shared__ float4 sk[TT];
    __shared__ float  sv[TT];

    const int tid = threadIdx.x;
    for (int i = tid; i < TT; i += TPB) {
        sk[i] = make_float4(ks[i], ks[TT + i], ks[2 * TT + i], ks[3 * TT + i]);
        sv[i] = v0t[i];
    }
    __syncthreads();

    const int tile = blockIdx.x * TILE;
    if (tile >= E) return;

    int   seg = -1;      // sentinel: first HANDLE always sets it
    float acc = 0.0f;

    const float4* __restrict__ nodes = g_nodes;

    if (tile + TILE <= E) {
        #pragma unroll
        for (int it = 0; it < ITERS; ++it) {
            const int e = tile + it * (TPB * VEC) + tid * VEC;
            int4 ia = __ldcs((const int4*)(map0 + e));
            int4 ja = __ldcs((const int4*)(map1 + e));
            int4 bt = __ldcs((const int4*)(batch + e));

            float V0, V1, V2, V3;
            EDGE_V(ia.x, ja.x, V0);
            EDGE_V(ia.y, ja.y, V1);
            EDGE_V(ia.z, ja.z, V2);
            EDGE_V(ia.w, ja.w, V3);

            if (bt.w == seg) {                 // sorted => whole group == seg
                acc += (V0 + V1) + (V2 + V3);
            } else {
                HANDLE1(bt.x, V0);
                HANDLE1(bt.y, V1);
                HANDLE1(bt.z, V2);
                HANDLE1(bt.w, V3);
            }
        }
    } else {
        for (int it = 0; it < ITERS; ++it) {
            int e = tile + it * (TPB * VEC) + tid * VEC;
            for (int kk = 0; kk < VEC; ++kk) {
                int ee = e + kk;
                if (ee >= E) break;
                int ii = __ldcs(map0 + ee);
                int jj = __ldcs(map1 + ee);
                int bi = __ldcs(batch + ee);
                float V;
                EDGE_V(ii, jj, V);
                HANDLE1(bi, V);
            }
        }
    }

    flush_acc(out, seg, acc);
}

// ---------------------------------------------------------------------------
// Launch
// ---------------------------------------------------------------------------
extern "C" void kernel_launch(void* const* d_in, const int* in_sizes, int n_in,
                              void* d_out, int out_size)
{
    const float* pos        = (const float*)d_in[0];
    const float* ks         = (const float*)d_in[1];
    const float* v0t        = (const float*)d_in[2];
    const int*   mapping    = (const int*)d_in[3];
    const int*   atom_types = (const int*)d_in[4];
    const int*   batch      = (const int*)d_in[5];

    const int N = in_sizes[0] / 3;
    const int E = in_sizes[3] / 2;
    const int G = out_size;

    float* out = (float*)d_out;

    int prepThreads = (N > G) ? N : G;
    int prepBlocks  = (prepThreads + TPB - 1) / TPB;
    prep_kernel<<<prepBlocks, TPB>>>(pos, atom_types, out, N, G);

    int blocks = (E + TILE - 1) / TILE;
    edge_kernel<<<blocks, TPB>>>(mapping, mapping + E, batch, ks, v0t, out, E);
}